// round 16
// baseline (speedup 1.0000x reference)
#include <cuda_runtime.h>
#include <cuda_bf16.h>
#include <cstdint>

// Problem constants (from reference)
#define BATCH 512
#define CH    12
#define TLEN  4096
#define TD    1024     // TLEN / 4 (downsampled)
#define KS    51
#define STEPS 7

// Scratch (static device globals; no allocation)
__device__ float g_vec[BATCH * TD];   // integrated, x4-scaled downsampled field
__device__ float g_h4[64];            // polyphase table h4[k*4+r], k=0..15

// ---------------------------------------------------------------------------
// Flow kernel: downsample + VecInt(7), branchless mask formula (bit-exact vs
// reference). 512 threads x 2 elems (strided 512): 4 CTAs/SM -> all 512 CTAs
// resident in ONE wave (no wave-quantization tail that the 1024-thr shape
// paid). Writes the x4-scaled field to g_vec (2 MB). Block 0 emits g_h4.
// ---------------------------------------------------------------------------
__global__ __launch_bounds__(512) void k_flow(const float* __restrict__ noise,
                                              const float* __restrict__ flow_mag,
                                              const float* __restrict__ sker) {
    __shared__ float buf[2][TD];
    __shared__ float ker_s[52];

    const int b   = blockIdx.x;
    const int tid = threadIdx.x;
    const float mag = flow_mag[0];
    const float INV_TD1 = 1.0f / (float)(TD - 1);

    // ---- init: resize_linear(flow_field, 0.25) -> src = 4q+1.5, i0 = 4q+1,
    //      w = 0.5 ; resize_transform(<1): *0.25 ; VecInt /2^7
    float f[2];
    {
        const float* nrow = noise + (size_t)b * TLEN;
        #pragma unroll
        for (int j = 0; j < 2; ++j) {
            int q = tid + 512 * j;
            float n0 = nrow[4 * q + 1];
            float n1 = nrow[4 * q + 2];
            float pf = 0.25f * ((mag * n0) * 0.5f + (mag * n1) * 0.5f);
            f[j] = pf * (1.0f / 128.0f);
            buf[0][q] = f[j];
        }
    }
    if (tid < 51) ker_s[tid] = sker[tid];
    __syncthreads();

    // ---- block 0: composite polyphase kernel h[r][m], m = k-7 in [-7,8]
    //      flow[4p+r] = sum_m h[r][m] * (4*vec[p+m])   (interior)
    if (b == 0 && tid < 64) {
        const int r = tid >> 4;
        const int k = tid & 15;
        const int m = k - 7;
        const float W[4] = {0.625f, 0.875f, 0.125f, 0.375f};
        float acc = 0.0f;
        for (int j = -25; j <= 25; ++j) {
            int srp = r + j + 100;            // sr + 100, 100 % 4 == 0
            int p   = srp / 4 - 25;           // floor_div(sr, 4)
            int rho = srp & 3;
            int d   = (rho >= 2) ? 0 : -1;
            float w = W[rho];
            float g = ker_s[j + 25];
            int tgt = p + d;
            if (tgt == m)     acc += g * (1.0f - w);
            if (tgt + 1 == m) acc += g * w;
        }
        g_h4[k * 4 + r] = acc;
    }

    // ---- VecInt: 7 scaling-and-squaring steps (branchless, bit-exact)
    int cur = 0;
    #pragma unroll
    for (int it = 0; it < STEPS; ++it) {
        const float* bc = buf[cur];
        float* bn = buf[1 - cur];
        #pragma unroll
        for (int j = 0; j < 2; ++j) {
            int q = tid + 512 * j;
            float nl = (float)q + f[j];

            float ixn = nl * INV_TD1;
            float xw = fminf(fminf(ixn + 1.0f, 2.0f - ixn), 1.0f);
            xw = fmaxf(xw, 0.0f);

            float y0 = floorf(nl);
            float fy = nl - y0;
            int y0i = (int)y0;
            int y1i = y0i + 1;
            float m0 = (y0i >= 0 && y0i < TD) ? 1.0f : 0.0f;
            float m1 = (y1i >= 0 && y1i < TD) ? 1.0f : 0.0f;
            int y0c = min(max(y0i, 0), TD - 1);
            int y1c = min(max(y1i, 0), TD - 1);
            float g0 = bc[y0c];
            float g1 = bc[y1c];
            float warped = xw * ((1.0f - fy) * (m0 * g0) + fy * (m1 * g1));
            f[j] = f[j] + warped;
            bn[q] = f[j];
        }
        cur ^= 1;
        __syncthreads();
    }

    // ---- publish x4-scaled field (resize_transform >1: magnitude x4)
    float* vrow = g_vec + (size_t)b * TD;
    #pragma unroll
    for (int j = 0; j < 2; ++j)
        vrow[tid + 512 * j] = 4.0f * f[j];
}

// ---------------------------------------------------------------------------
// Warp kernel (R14 measured-best body, prefetch removed). Each CTA covers 256
// consecutive t of one row: stage the 79-float vec window + h4 table in smem,
// evaluate the 16-tap phase sum (identical FMA order -> bit-identical flow),
// then gather/store all 12 channels.
// ---------------------------------------------------------------------------
__global__ __launch_bounds__(256) void k_warp(const float* __restrict__ src,
                                              const float* __restrict__ sker,
                                              float* __restrict__ out) {
    __shared__ float win[80];     // vec[qbase-7 .. qbase+71], zero-padded
    __shared__ float h4_s[64];

    const int tid = threadIdx.x;
    const int blk = blockIdx.x;            // over (BATCH*TLEN)/256
    const int b   = blk >> 4;              // 16 chunks per row
    const int t0  = (blk & 15) << 8;       // chunk start (t)
    const int qb  = t0 >> 2;               // chunk start (q)
    const int t   = t0 + tid;

    const float* vrow = g_vec + (size_t)b * TD;
    if (tid < 64) h4_s[tid] = g_h4[tid];
    if (tid < 79) {
        int q = qb - 7 + tid;
        win[tid] = (q >= 0 && q < TD) ? __ldg(vrow + q) : 0.0f;
    }
    __syncthreads();

    // ---- polyphase conv for this t: r = t&3, window base = tid>>2
    float fl;
    {
        const int r  = tid & 3;
        const int wb = tid >> 2;
        float acc = 0.0f;
        #pragma unroll
        for (int k = 0; k < 16; ++k)
            acc += h4_s[k * 4 + r] * win[wb + k];

        // Boundary corrections (R7 derivation): only t<28 or t>=4068.
        if (t < 28 || t >= 4068) {
            float v0 = __ldg(vrow);
            float vL = __ldg(vrow + (TD - 1));
            auto G = [&](int jj) -> float {
                return (jj >= -25 && jj <= 25) ? __ldg(sker + jj + 25) : 0.0f;
            };
            acc += v0 * (0.375f * (G(-t)      - G(-1 - t))
                       + 0.125f * (G(1 - t)   - G(-2 - t)))
                 + vL * (0.125f * G(4094 - t) + 0.375f * G(4095 - t)
                       - 0.375f * G(4096 - t) - 0.125f * G(4097 - t));
        }
        fl = acc;
    }

    // ---- exact reference fp coordinate sequence
    float nl = (float)t + fl;
    float v  = 2.0f * (nl / (float)(TLEN - 1) - 0.5f);
    float ix = (v + 1.0f) * 0.5f;
    float iy = (v + 1.0f) * 0.5f * (float)(TLEN - 1);

    float xw = fminf(fminf(ix + 1.0f, 2.0f - ix), 1.0f);
    xw = fmaxf(xw, 0.0f);

    float y0 = floorf(iy);
    float fy = iy - y0;
    int y0i = (int)y0;
    int y1i = y0i + 1;
    float a0 = xw * (1.0f - fy) * ((y0i >= 0 && y0i < TLEN) ? 1.0f : 0.0f);
    float a1 = xw * fy         * ((y1i >= 0 && y1i < TLEN) ? 1.0f : 0.0f);
    int y0c = min(max(y0i, 0), TLEN - 1);
    int y1c = min(max(y1i, 0), TLEN - 1);

    const float* sb = src + (size_t)b * (CH * TLEN);
    float*       ob = out + (size_t)b * (CH * TLEN) + t;

    // Batch all gather loads first for maximum MLP, then compute + store.
    float g0v[CH], g1v[CH];
    #pragma unroll
    for (int c = 0; c < CH; ++c) {
        const float* sc = sb + c * TLEN;
        g0v[c] = __ldg(sc + y0c);
        g1v[c] = __ldg(sc + y1c);
    }
    #pragma unroll
    for (int c = 0; c < CH; ++c) {
        ob[c * TLEN] = a0 * g0v[c] + a1 * g1v[c];
    }
}

// ---------------------------------------------------------------------------
extern "C" void kernel_launch(void* const* d_in, const int* in_sizes, int n_in,
                              void* d_out, int out_size) {
    const float* source    = (const float*)d_in[0];  // [512,12,4096]
    const float* flow_mag  = (const float*)d_in[1];  // [1]
    const float* noise     = (const float*)d_in[2];  // [512,1,4096]
    const float* smooth_k  = (const float*)d_in[3];  // [51]
    float*       out       = (float*)d_out;          // [512,12,4096]

    k_flow<<<BATCH, 512>>>(noise, flow_mag, smooth_k);
    k_warp<<<(BATCH * TLEN) / 256, 256>>>(source, smooth_k, out);
}